// round 11
// baseline (speedup 1.0000x reference)
#include <cuda_runtime.h>
#include <cuda_fp16.h>
#include <math.h>
#include <stdint.h>

#define M_TOTAL 32768
#define E_DIM   512
#define F_DIM   2048

// ---------------- global scratch ----------------
// fp16 W2 copy [E][F] and fp16 H buffer [M][F], both as uint4 (8 halves)
__device__ uint4 g_W2h[E_DIM * F_DIM / 8];
__device__ uint4 g_H[(size_t)M_TOTAL * F_DIM / 8];

// ---------------- helpers ----------------
static __device__ __forceinline__ uint32_t cvta_smem(const void* p) {
    uint32_t a;
    asm("{ .reg .u64 t; cvta.to.shared.u64 t, %1; cvt.u32.u64 %0, t; }" : "=r"(a) : "l"(p));
    return a;
}
static __device__ __forceinline__ void cpasync16(uint32_t dst, const void* src) {
    asm volatile("cp.async.ca.shared.global [%0], [%1], 16;"
                 :: "r"(dst), "l"(src) : "memory");
}
static __device__ __forceinline__ void ldsm4(uint32_t* r, uint32_t a) {
    asm volatile("ldmatrix.sync.aligned.m8n8.x4.shared.b16 {%0,%1,%2,%3}, [%4];"
                 : "=r"(r[0]), "=r"(r[1]), "=r"(r[2]), "=r"(r[3]) : "r"(a));
}
static __device__ __forceinline__ void mma_f16(float* c, const uint32_t* a,
                                               uint32_t b0, uint32_t b1) {
    asm volatile(
        "mma.sync.aligned.m16n8k16.row.col.f32.f16.f16.f32 "
        "{%0,%1,%2,%3},{%4,%5,%6,%7},{%8,%9},{%0,%1,%2,%3};"
        : "+f"(c[0]), "+f"(c[1]), "+f"(c[2]), "+f"(c[3])
        : "r"(a[0]), "r"(a[1]), "r"(a[2]), "r"(a[3]), "r"(b0), "r"(b1));
}

// ---------------- kernel 0: W2 -> fp16 ----------------
__global__ void cvt_w2_kernel(const float* __restrict__ W2) {
    int i = blockIdx.x * 256 + threadIdx.x;
    float4 v = ((const float4*)W2)[i];
    __half2* o = (__half2*)g_W2h;
    o[2 * i]     = __floats2half2_rn(v.x, v.y);
    o[2 * i + 1] = __floats2half2_rn(v.z, v.w);
}

// ---------------- kernel 1: H = relu(cos(2x+theta) . W1^T) -> fp16 ----------------
// CTA covers 64 m-rows; thread owns k-chunk [tid*8, tid*8+8), W1 slice in regs.
__global__ void __launch_bounds__(256, 2)
h_kernel(const float* __restrict__ x,
         const float* __restrict__ theta,
         const float* __restrict__ W1)
{
    __shared__ float sq[64 * 8];
    const int tid = threadIdx.x;
    const int m0 = blockIdx.x * 64;

    if (tid < 64) {
        const float* xr = x + (size_t)(m0 + tid) * E_DIM;
        float4 x0 = ((const float4*)xr)[0];
        float4 x1 = ((const float4*)xr)[1];
        float* qd = sq + tid * 8;
        qd[0] = cosf(2.0f * x0.x + __ldg(theta + 0));
        qd[1] = cosf(2.0f * x0.y + __ldg(theta + 1));
        qd[2] = cosf(2.0f * x0.z + __ldg(theta + 2));
        qd[3] = cosf(2.0f * x0.w + __ldg(theta + 3));
        qd[4] = cosf(2.0f * x1.x + __ldg(theta + 4));
        qd[5] = cosf(2.0f * x1.y + __ldg(theta + 5));
        qd[6] = cosf(2.0f * x1.z + __ldg(theta + 6));
        qd[7] = cosf(2.0f * x1.w + __ldg(theta + 7));
    }

    // W1 slice: rows tid*8 .. tid*8+7, each 8 floats -> 16 float4 regs (one-time load)
    float4 w[16];
    const float4* wp = (const float4*)W1 + (size_t)tid * 16;
    #pragma unroll
    for (int i = 0; i < 16; ++i) w[i] = __ldg(wp + i);

    __syncthreads();

    uint4* hdst = g_H + ((size_t)m0) * 256 + tid;
    #pragma unroll 4
    for (int r = 0; r < 64; ++r) {
        const float* qr = sq + r * 8;
        float4 qa = ((const float4*)qr)[0];
        float4 qb = ((const float4*)qr)[1];
        uint32_t pk[4];
        #pragma unroll
        for (int j = 0; j < 4; ++j) {
            float s[2];
            #pragma unroll
            for (int u = 0; u < 2; ++u) {
                float4 wa = w[(j * 2 + u) * 2];
                float4 wb = w[(j * 2 + u) * 2 + 1];
                float t = qa.x * wa.x;
                t = fmaf(qa.y, wa.y, t);
                t = fmaf(qa.z, wa.z, t);
                t = fmaf(qa.w, wa.w, t);
                t = fmaf(qb.x, wb.x, t);
                t = fmaf(qb.y, wb.y, t);
                t = fmaf(qb.z, wb.z, t);
                t = fmaf(qb.w, wb.w, t);
                s[u] = fmaxf(t, 0.0f);
            }
            __half2 h = __floats2half2_rn(s[0], s[1]);
            pk[j] = *(uint32_t*)&h;
        }
        hdst[(size_t)r * 256] = make_uint4(pk[0], pk[1], pk[2], pk[3]);
    }
}

// ---------------- kernel 2: out = H . W2h^T (fp16 MMA, fp32 acc) ----------------
#define BM 128
#define BN 128
#define BK 64
#define GK_ITERS 32          // 2048 / 64
#define STG 32768            // per-stage: A 16KB + B 16KB
#define SMEM_BYTES (3 * STG + 1024)

__global__ void __launch_bounds__(256, 2)
gemm2_kernel(float* __restrict__ out)
{
    extern __shared__ char dsm[];
    const uint32_t raw = cvta_smem(dsm);
    const uint32_t sbase = (raw + 1023) & ~1023u;

    const int tid  = threadIdx.x;
    const int warp = tid >> 5, lane = tid & 31;
    const int wm = warp >> 2, wn = warp & 3;        // 2 x 4 warp grid, tile 64x32
    const int mt = blockIdx.x >> 2, nt = blockIdx.x & 3;   // nt fastest -> A tile L2 reuse
    const int m0 = mt * BM, n0 = nt * BN;

    // ---- load mapping: row = tid>>1 (0..127), 4 x 16B chunks at cb..cb+3 ----
    const int row = tid >> 1;
    const int cb  = (tid & 1) * 4;
    const uint32_t aDst = sbase + row * 128;
    const uint32_t bDst = sbase + 16384 + row * 128;
    const uint4* gA = g_H + ((size_t)(m0 + row)) * 256 + cb;
    const uint4* gB = g_W2h + ((size_t)(n0 + row)) * 256 + cb;
    uint32_t coff[4];
    #pragma unroll
    for (int j = 0; j < 4; ++j)
        coff[j] = ((uint32_t)((cb + j) ^ (row & 7))) << 4;

    // ---- consumer fragment mapping (verified R6/R7) ----
    const int t8 = lane >> 3, r8 = lane & 7;
    const int aCrow = wm * 64 + (t8 & 1) * 8 + r8;
    const uint32_t aCx = (uint32_t)(aCrow & 7);
    const uint32_t aCbase = sbase + aCrow * 128;
    const int aCk = t8 >> 1;
    const int bCrow = wn * 32 + (t8 >> 1) * 8 + r8;
    const uint32_t bCx = (uint32_t)(bCrow & 7);
    const uint32_t bCbase = sbase + 16384 + bCrow * 128;
    const int bCk = t8 & 1;

    float acc[4][4][4];
    #pragma unroll
    for (int i = 0; i < 4; ++i)
        #pragma unroll
        for (int j = 0; j < 4; ++j)
            #pragma unroll
            for (int e = 0; e < 4; ++e) acc[i][j][e] = 0.0f;

    // ---- prologue: stages 0, 1 ----
    #pragma unroll
    for (int s = 0; s < 2; ++s) {
        const uint32_t so = (uint32_t)s * STG;
        #pragma unroll
        for (int j = 0; j < 4; ++j) {
            cpasync16(aDst + so + coff[j], gA + s * 8 + j);
            cpasync16(bDst + so + coff[j], gB + s * 8 + j);
        }
        asm volatile("cp.async.commit_group;" ::: "memory");
    }

    for (int it = 0; it < GK_ITERS; ++it) {
        if (it < GK_ITERS - 1) {
            asm volatile("cp.async.wait_group 1;" ::: "memory");
        } else {
            asm volatile("cp.async.wait_group 0;" ::: "memory");
        }
        __syncthreads();

        // issue stage it+2 (slot consumed at it-1; barrier above protects it)
        if (it + 2 < GK_ITERS) {
            const int s = it + 2;
            const uint32_t so = (uint32_t)(s % 3) * STG;
            #pragma unroll
            for (int j = 0; j < 4; ++j) {
                cpasync16(aDst + so + coff[j], gA + s * 8 + j);
                cpasync16(bDst + so + coff[j], gB + s * 8 + j);
            }
            asm volatile("cp.async.commit_group;" ::: "memory");
        }

        // consume stage it
        const uint32_t so = (uint32_t)(it % 3) * STG;
        #pragma unroll
        for (int ks = 0; ks < 4; ++ks) {
            uint32_t a[4][4];
            #pragma unroll
            for (int im = 0; im < 4; ++im)
                ldsm4(a[im], aCbase + so + im * 2048 +
                             ((((uint32_t)(ks * 2 + aCk)) ^ aCx) << 4));
            uint32_t bb[2][4];
            #pragma unroll
            for (int jp = 0; jp < 2; ++jp)
                ldsm4(bb[jp], bCbase + so + jp * 2048 +
                              ((((uint32_t)(ks * 2 + bCk)) ^ bCx) << 4));
            #pragma unroll
            for (int im = 0; im < 4; ++im)
                #pragma unroll
                for (int jn = 0; jn < 4; ++jn)
                    mma_f16(acc[im][jn], a[im],
                            bb[jn >> 1][(jn & 1) * 2], bb[jn >> 1][(jn & 1) * 2 + 1]);
        }
    }

    // ---- epilogue ----
    const int g = lane >> 2, tq = lane & 3;
    #pragma unroll
    for (int im = 0; im < 4; ++im) {
        const int row0 = m0 + wm * 64 + im * 16 + g;
        #pragma unroll
        for (int jn = 0; jn < 4; ++jn) {
            const int col = n0 + wn * 32 + jn * 8 + tq * 2;
            *(float2*)(out + (size_t)row0 * E_DIM + col) =
                make_float2(acc[im][jn][0], acc[im][jn][1]);
            *(float2*)(out + (size_t)(row0 + 8) * E_DIM + col) =
                make_float2(acc[im][jn][2], acc[im][jn][3]);
        }
    }
}

extern "C" void kernel_launch(void* const* d_in, const int* in_sizes, int n_in,
                              void* d_out, int out_size) {
    const float* x     = (const float*)d_in[0];
    const float* theta = (const float*)d_in[1];
    const float* W1    = (const float*)d_in[2];
    const float* W2    = (const float*)d_in[3];
    float* out = (float*)d_out;

    cvt_w2_kernel<<<(E_DIM * F_DIM / 4) / 256, 256>>>(W2);
    h_kernel<<<M_TOTAL / 64, 256>>>(x, theta, W1);

    cudaFuncSetAttribute(gemm2_kernel, cudaFuncAttributeMaxDynamicSharedMemorySize, SMEM_BYTES);
    dim3 grid((M_TOTAL / BM) * (E_DIM / BN));   // 256 * 4 = 1024 CTAs
    gemm2_kernel<<<grid, 256, SMEM_BYTES>>>(out);
}

// round 13
// speedup vs baseline: 1.3133x; 1.3133x over previous
#include <cuda_runtime.h>
#include <cuda_fp16.h>
#include <math.h>
#include <stdint.h>

#define M_TOTAL 32768
#define E_DIM   512
#define F_DIM   2048

#define BM 128
#define BN 256
#define BK 64
#define THREADS 256
#define K_ITERS 32

// smem offsets (relative to 1024-aligned base)
#define SQ   0            // q fp32 [128][8] = 4096
#define SA0  4096         // A (H fp16) [128 rows][128B] dbl: 2 x 16384
#define SAB  16384
#define SB0  36864        // B (W2 fp16) [256 rows][128B] dbl: 2 x 32768
#define SBB  32768
#define SMEM_BYTES (102400 + 1024)

// fp16 copy of W2 (E x F), row-major [n][k], uint4 = 8 halves
__device__ uint4 g_W2h[E_DIM * F_DIM / 8];

__global__ void cvt_w2_kernel(const float* __restrict__ W2) {
    int i = blockIdx.x * 256 + threadIdx.x;
    float4 v = ((const float4*)W2)[i];
    __half2* o = (__half2*)g_W2h;
    o[2 * i]     = __floats2half2_rn(v.x, v.y);
    o[2 * i + 1] = __floats2half2_rn(v.z, v.w);
}

static __device__ __forceinline__ uint32_t cvta_smem(const void* p) {
    uint32_t a;
    asm("{ .reg .u64 t; cvta.to.shared.u64 t, %1; cvt.u32.u64 %0, t; }" : "=r"(a) : "l"(p));
    return a;
}
static __device__ __forceinline__ void sts128(uint32_t addr, uint32_t r0, uint32_t r1,
                                              uint32_t r2, uint32_t r3) {
    asm volatile("st.shared.v4.b32 [%0], {%1,%2,%3,%4};"
                 :: "r"(addr), "r"(r0), "r"(r1), "r"(r2), "r"(r3) : "memory");
}
static __device__ __forceinline__ void cpasync16(uint32_t dst, const void* src) {
    asm volatile("cp.async.ca.shared.global [%0], [%1], 16;"
                 :: "r"(dst), "l"(src) : "memory");
}
static __device__ __forceinline__ void ldsm4(uint32_t* r, uint32_t a) {
    asm volatile("ldmatrix.sync.aligned.m8n8.x4.shared.b16 {%0,%1,%2,%3}, [%4];"
                 : "=r"(r[0]), "=r"(r[1]), "=r"(r[2]), "=r"(r[3]) : "r"(a));
}
static __device__ __forceinline__ void mma_f16(float* c, const uint32_t* a,
                                               uint32_t b0, uint32_t b1) {
    asm volatile(
        "mma.sync.aligned.m16n8k16.row.col.f32.f16.f16.f32 "
        "{%0,%1,%2,%3},{%4,%5,%6,%7},{%8,%9},{%0,%1,%2,%3};"
        : "+f"(c[0]), "+f"(c[1]), "+f"(c[2]), "+f"(c[3])
        : "r"(a[0]), "r"(a[1]), "r"(a[2]), "r"(a[3]), "r"(b0), "r"(b1));
}
static __device__ __forceinline__ float dot8(const float4& qa, const float4& qb,
                                             const float4& wa, const float4& wb) {
    float t = qa.x * wa.x;
    t = fmaf(qa.y, wa.y, t);
    t = fmaf(qa.z, wa.z, t);
    t = fmaf(qa.w, wa.w, t);
    t = fmaf(qb.x, wb.x, t);
    t = fmaf(qb.y, wb.y, t);
    t = fmaf(qb.z, wb.z, t);
    t = fmaf(qb.w, wb.w, t);
    return t;
}

__global__ void __launch_bounds__(THREADS, 1)
ffq_kernel(const float* __restrict__ x,
           const float* __restrict__ theta,
           const float* __restrict__ W1,
           float* __restrict__ out)
{
    extern __shared__ char dsm[];
    const uint32_t raw = cvta_smem(dsm);
    const uint32_t sbase = (raw + 1023) & ~1023u;
    char* gb = dsm + (sbase - raw);

    const int tid  = threadIdx.x;
    const int warp = tid >> 5, lane = tid & 31;
    const int wm = warp >> 2, wn = warp & 3;     // consumer: 2 x 4 grid, warp tile 64x64
    const int mt = blockIdx.x >> 1, nt = blockIdx.x & 1;
    const int m0 = mt * BM, n0 = nt * BN;

    // ---- q = cos(2*x[:, :8] + theta) into smem (rows 0..127) ----
    if (tid < BM) {
        const float* xr = x + (size_t)(m0 + tid) * E_DIM;
        float4 x0 = ((const float4*)xr)[0];
        float4 x1 = ((const float4*)xr)[1];
        float* qd = (float*)(gb + SQ) + tid * 8;
        qd[0] = cosf(2.0f * x0.x + __ldg(theta + 0));
        qd[1] = cosf(2.0f * x0.y + __ldg(theta + 1));
        qd[2] = cosf(2.0f * x0.z + __ldg(theta + 2));
        qd[3] = cosf(2.0f * x0.w + __ldg(theta + 3));
        qd[4] = cosf(2.0f * x1.x + __ldg(theta + 4));
        qd[5] = cosf(2.0f * x1.y + __ldg(theta + 5));
        qd[6] = cosf(2.0f * x1.z + __ldg(theta + 6));
        qd[7] = cosf(2.0f * x1.w + __ldg(theta + 7));
    }
    __syncthreads();

    // ---- A producer constants: thread covers rows R, R+64 and k8-groups g0, g0+1 ----
    const int g0 = (warp & 3) * 2;               // k8 group (16B column index), warp-uniform
    const int R  = ((warp >> 2) << 5) + lane;    // 0..63
    const int R1 = R + 64;
    float4 qa0, qa1, qb0, qb1;
    {
        const float* qp = (const float*)(gb + SQ);
        qa0 = ((const float4*)(qp + R * 8))[0];
        qa1 = ((const float4*)(qp + R * 8))[1];
        qb0 = ((const float4*)(qp + R1 * 8))[0];
        qb1 = ((const float4*)(qp + R1 * 8))[1];
    }
    // A STS addresses for (row, g) with swizzle c^(row&7)
    const uint32_t aP00 = sbase + SA0 + R  * 128 + (((uint32_t)(g0       ^ (R  & 7))) << 4);
    const uint32_t aP01 = sbase + SA0 + R  * 128 + (((uint32_t)((g0 + 1) ^ (R  & 7))) << 4);
    const uint32_t aP10 = sbase + SA0 + R1 * 128 + (((uint32_t)(g0       ^ (R1 & 7))) << 4);
    const uint32_t aP11 = sbase + SA0 + R1 * 128 + (((uint32_t)((g0 + 1) ^ (R1 & 7))) << 4);

    // ---- B producer constants: row = tid, 8 x 16B chunks via cp.async ----
    const uint32_t bRow = sbase + SB0 + tid * 128;
    const uint4* w2p = g_W2h + (size_t)(n0 + tid) * 256;
    uint32_t bcoff[8];
    #pragma unroll
    for (int c = 0; c < 8; ++c)
        bcoff[c] = ((uint32_t)(c ^ (tid & 7))) << 4;

    // ---- consumer constants (R7-verified BK=64 fragment mapping) ----
    const int t8 = lane >> 3, r8 = lane & 7;
    const int aCrow = wm * 64 + (t8 & 1) * 8 + r8;
    const uint32_t aCx = (uint32_t)(aCrow & 7);
    const uint32_t aCbase = sbase + SA0 + aCrow * 128;
    const int aCk = t8 >> 1;
    const int bCrow = wn * 64 + (t8 >> 1) * 8 + r8;
    const uint32_t bCx = (uint32_t)(bCrow & 7);
    const uint32_t bCbase = sbase + SB0 + bCrow * 128;
    const int bCk = t8 & 1;

    float acc[4][8][4];
    #pragma unroll
    for (int i = 0; i < 4; ++i)
        #pragma unroll
        for (int j = 0; j < 8; ++j)
            #pragma unroll
            for (int e = 0; e < 4; ++e) acc[i][j][e] = 0.0f;

    // ---- prologue: B(0) via cp.async; A(0) produced; wait; sync ----
    {
        #pragma unroll
        for (int c = 0; c < 8; ++c)
            cpasync16(bRow + bcoff[c], w2p + c);
        asm volatile("cp.async.commit_group;" ::: "memory");

        #pragma unroll
        for (int gsel = 0; gsel < 2; ++gsel) {
            const int g = g0 + gsel;
            const float* wrow = W1 + (size_t)(g * 8) * 8;
            uint32_t pkA[4], pkB[4];
            #pragma unroll
            for (int j = 0; j < 4; ++j) {
                float sa[2], sb[2];
                #pragma unroll
                for (int u = 0; u < 2; ++u) {
                    float4 wa = ((const float4*)(wrow + (j * 2 + u) * 8))[0];
                    float4 wb = ((const float4*)(wrow + (j * 2 + u) * 8))[1];
                    sa[u] = fmaxf(dot8(qa0, qa1, wa, wb), 0.0f);
                    sb[u] = fmaxf(dot8(qb0, qb1, wa, wb), 0.0f);
                }
                __half2 ha = __floats2half2_rn(sa[0], sa[1]);
                __half2 hb = __floats2half2_rn(sb[0], sb[1]);
                pkA[j] = *(uint32_t*)&ha;
                pkB[j] = *(uint32_t*)&hb;
            }
            sts128(gsel ? aP01 : aP00, pkA[0], pkA[1], pkA[2], pkA[3]);
            sts128(gsel ? aP11 : aP10, pkB[0], pkB[1], pkB[2], pkB[3]);
        }
        asm volatile("cp.async.wait_group 0;" ::: "memory");
    }
    __syncthreads();

    for (int it = 0; it < K_ITERS; ++it) {
        const int b = it & 1, nb = b ^ 1;
        const bool dp = (it + 1 < K_ITERS);
        const int kkn = (it + 1) * BK;

        // ---- top: kick off next B chunk (async) ----
        if (dp) {
            const uint32_t o = (uint32_t)nb * SBB;
            const uint4* src = w2p + (size_t)(kkn >> 3);
            #pragma unroll
            for (int c = 0; c < 8; ++c)
                cpasync16(bRow + o + bcoff[c], src + c);
            asm volatile("cp.async.commit_group;" ::: "memory");
        }

        // ---- consume buffer b: 4 k16 blocks ----
        const uint32_t aoff = (uint32_t)b * SAB;
        const uint32_t boff = (uint32_t)b * SBB;
        #pragma unroll
        for (int ks = 0; ks < 4; ++ks) {
            uint32_t a[4][4];
            #pragma unroll
            for (int im = 0; im < 4; ++im)
                ldsm4(a[im], aCbase + aoff + im * 2048 +
                             ((((uint32_t)(ks * 2 + aCk)) ^ aCx) << 4));
            uint32_t bb[4][4];
            #pragma unroll
            for (int jp = 0; jp < 4; ++jp)
                ldsm4(bb[jp], bCbase + boff + jp * 2048 +
                              ((((uint32_t)(ks * 2 + bCk)) ^ bCx) << 4));
            #pragma unroll
            for (int im = 0; im < 4; ++im)
                #pragma unroll
                for (int jn = 0; jn < 8; ++jn)
                    mma_f16(acc[im][jn], a[im],
                            bb[jn >> 1][(jn & 1) * 2], bb[jn >> 1][(jn & 1) * 2 + 1]);
        }

        // ---- produce A(it+1) into buffer nb ----
        if (dp) {
            const uint32_t o = (uint32_t)nb * SAB;
            #pragma unroll
            for (int gsel = 0; gsel < 2; ++gsel) {
                const int g = g0 + gsel;
                const float* wrow = W1 + (size_t)(kkn + g * 8) * 8;
                uint32_t pkA[4], pkB[4];
                #pragma unroll
                for (int j = 0; j < 4; ++j) {
                    float sa[2], sb[2];
                    #pragma unroll
                    for (int u = 0; u < 2; ++u) {
                        float4 wa = ((const float4*)(wrow + (j * 2 + u) * 8))[0];
                        float4 wb = ((const float4*)(wrow + (j * 2 + u) * 8))[1];
                        sa[u] = fmaxf(dot8(qa0, qa1, wa, wb), 0.0f);
                        sb[u] = fmaxf(dot8(qb0, qb1, wa, wb), 0.0f);
                    }
                    __half2 ha = __floats2half2_rn(sa[0], sa[1]);
                    __half2 hb = __floats2half2_rn(sb[0], sb[1]);
                    pkA[j] = *(uint32_t*)&ha;
                    pkB[j] = *(uint32_t*)&hb;
                }
                sts128((gsel ? aP01 : aP00) + o, pkA[0], pkA[1], pkA[2], pkA[3]);
                sts128((gsel ? aP11 : aP10) + o, pkB[0], pkB[1], pkB[2], pkB[3]);
            }
            asm volatile("cp.async.wait_group 0;" ::: "memory");
        }
        __syncthreads();
    }

    // ---- epilogue: acc -> out (R5/R7-verified mapping) ----
    const int g = lane >> 2, tq = lane & 3;
    #pragma unroll
    for (int im = 0; im < 4; ++im) {
        const int row0 = m0 + wm * 64 + im * 16 + g;
        #pragma unroll
        for (int jn = 0; jn < 8; ++jn) {
            const int col = n0 + wn * 64 + jn * 8 + tq * 2;
            *(float2*)(out + (size_t)row0 * E_DIM + col) =
                make_float2(acc[im][jn][0], acc[im][jn][1]);
            *(float2*)(out + (size_t)(row0 + 8) * E_DIM + col) =
                make_float2(acc[im][jn][2], acc[im][jn][3]);
        }
    }
}

extern "C" void kernel_launch(void* const* d_in, const int* in_sizes, int n_in,
                              void* d_out, int out_size) {
    const float* x     = (const float*)d_in[0];
    const float* theta = (const float*)d_in[1];
    const float* W1    = (const float*)d_in[2];
    const float* W2    = (const float*)d_in[3];
    float* out = (float*)d_out;

    cvt_w2_kernel<<<(E_DIM * F_DIM / 4) / 256, 256>>>(W2);

    cudaFuncSetAttribute(ffq_kernel, cudaFuncAttributeMaxDynamicSharedMemorySize, SMEM_BYTES);
    dim3 grid((M_TOTAL / BM) * (E_DIM / BN));   // 256 * 2 = 512 CTAs
    ffq_kernel<<<grid, THREADS, SMEM_BYTES>>>(x, theta, W1, out);
}

// round 14
// speedup vs baseline: 1.4746x; 1.1229x over previous
#include <cuda_runtime.h>
#include <cuda_fp16.h>
#include <math.h>
#include <stdint.h>

#define M_TOTAL 32768
#define E_DIM   512
#define F_DIM   2048

#define BM 128
#define BN 256
#define BK 32
#define THREADS 256
#define K_ITERS 64

// smem offsets (relative to 1024-aligned base)
#define SA0  0            // A (H fp16) [128 rows][64B] dbl: 2 x 8192
#define SAB  8192
#define SB0  16384        // B (W2 fp16) [256 rows][64B] dbl: 2 x 16384
#define SBB  16384
#define SMEM_BYTES (49152 + 1024)

// fp16 copy of W2 (E x F), row-major [n][k], uint4 = 8 halves
__device__ uint4 g_W2h[E_DIM * F_DIM / 8];

__global__ void cvt_w2_kernel(const float* __restrict__ W2) {
    int i = blockIdx.x * 256 + threadIdx.x;
    float4 v = ((const float4*)W2)[i];
    __half2* o = (__half2*)g_W2h;
    o[2 * i]     = __floats2half2_rn(v.x, v.y);
    o[2 * i + 1] = __floats2half2_rn(v.z, v.w);
}

static __device__ __forceinline__ uint32_t cvta_smem(const void* p) {
    uint32_t a;
    asm("{ .reg .u64 t; cvta.to.shared.u64 t, %1; cvt.u32.u64 %0, t; }" : "=r"(a) : "l"(p));
    return a;
}
static __device__ __forceinline__ void sts32(uint32_t addr, uint32_t v) {
    asm volatile("st.shared.b32 [%0], %1;" :: "r"(addr), "r"(v) : "memory");
}
static __device__ __forceinline__ void cpasync16(uint32_t dst, const void* src) {
    asm volatile("cp.async.ca.shared.global [%0], [%1], 16;"
                 :: "r"(dst), "l"(src) : "memory");
}
static __device__ __forceinline__ void ldsm4(uint32_t* r, uint32_t a) {
    asm volatile("ldmatrix.sync.aligned.m8n8.x4.shared.b16 {%0,%1,%2,%3}, [%4];"
                 : "=r"(r[0]), "=r"(r[1]), "=r"(r[2]), "=r"(r[3]) : "r"(a));
}
static __device__ __forceinline__ void mma_f16(float* c, const uint32_t* a,
                                               uint32_t b0, uint32_t b1) {
    asm volatile(
        "mma.sync.aligned.m16n8k16.row.col.f32.f16.f16.f32 "
        "{%0,%1,%2,%3},{%4,%5,%6,%7},{%8,%9},{%0,%1,%2,%3};"
        : "+f"(c[0]), "+f"(c[1]), "+f"(c[2]), "+f"(c[3])
        : "r"(a[0]), "r"(a[1]), "r"(a[2]), "r"(a[3]), "r"(b0), "r"(b1));
}
// d = A(k16, upper 8 zero) * B(n8k16, upper k zero); c = 0
static __device__ __forceinline__ void mma_f16_z(float* d, uint32_t a0, uint32_t a1,
                                                 uint32_t b0) {
    asm volatile(
        "mma.sync.aligned.m16n8k16.row.col.f32.f16.f16.f32 "
        "{%0,%1,%2,%3},{%4,%5,%6,%6},{%7,%6},{%8,%8,%8,%8};"
        : "=f"(d[0]), "=f"(d[1]), "=f"(d[2]), "=f"(d[3])
        : "r"(a0), "r"(a1), "r"(0u), "r"(b0), "f"(0.0f));
}

__global__ void __launch_bounds__(THREADS, 1)
ffq_kernel(const float* __restrict__ x,
           const float* __restrict__ theta,
           const float* __restrict__ W1,
           float* __restrict__ out)
{
    extern __shared__ char dsm[];
    const uint32_t raw = cvta_smem(dsm);
    const uint32_t sbase = (raw + 1023) & ~1023u;

    const int tid  = threadIdx.x;
    const int warp = tid >> 5, lane = tid & 31;
    const int g = lane >> 2, tq = lane & 3;
    const int wm = warp >> 2, wn = warp & 3;     // consumer: 2 x 4 grid, warp tile 64x64
    const int mt = blockIdx.x >> 1, nt = blockIdx.x & 1;
    const int m0 = mt * BM, n0 = nt * BN;

    // ---- q A-fragment (computed once, lives in 2 regs): rows pr, pr+8; k=2tq,2tq+1 ----
    const int pr = warp * 16 + g;                // producer m-row (0..127 across 8 warps)
    uint32_t qf0, qf1;
    {
        const float t0 = __ldg(theta + 2 * tq);
        const float t1 = __ldg(theta + 2 * tq + 1);
        float2 v0 = *(const float2*)(x + (size_t)(m0 + pr) * E_DIM + 2 * tq);
        float2 v1 = *(const float2*)(x + (size_t)(m0 + pr + 8) * E_DIM + 2 * tq);
        __half2 h0 = __floats2half2_rn(cosf(2.0f * v0.x + t0), cosf(2.0f * v0.y + t1));
        __half2 h1 = __floats2half2_rn(cosf(2.0f * v1.x + t0), cosf(2.0f * v1.y + t1));
        qf0 = *(uint32_t*)&h0;
        qf1 = *(uint32_t*)&h1;
    }

    // ---- producer STS bases: A tile [128][64B], swizzle chunk^( (row>>1)&3 ) ----
    const uint32_t sw0 = (uint32_t)((pr >> 1) & 3);
    const uint32_t sw1 = (uint32_t)(((pr + 8) >> 1) & 3);
    const uint32_t pBase0 = sbase + SA0 + pr * 64 + tq * 4;
    const uint32_t pBase1 = sbase + SA0 + (pr + 8) * 64 + tq * 4;

    // ---- B producer: row = tid, 4 x 16B chunks via cp.async ----
    const uint32_t bRow = sbase + SB0 + tid * 64;
    const uint4* w2p = g_W2h + (size_t)(n0 + tid) * 256;
    uint32_t bcoff[4];
    #pragma unroll
    for (int c = 0; c < 4; ++c)
        bcoff[c] = ((uint32_t)(c ^ ((tid >> 1) & 3))) << 4;

    // ---- consumer constants (R5-verified) ----
    const int t8 = lane >> 3, r8 = lane & 7;
    const int aCrow = wm * 64 + (t8 & 1) * 8 + r8;
    const uint32_t aCs = (aCrow >> 1) & 3;
    const uint32_t aCbase = sbase + SA0 + aCrow * 64;
    const int aCk = t8 >> 1;
    const int bCrow = wn * 64 + (t8 >> 1) * 8 + r8;
    const uint32_t bCs = (bCrow >> 1) & 3;
    const uint32_t bCbase = sbase + SB0 + bCrow * 64;
    const int bCk = t8 & 1;

    float acc[4][8][4];
    #pragma unroll
    for (int i = 0; i < 4; ++i)
        #pragma unroll
        for (int j = 0; j < 8; ++j)
            #pragma unroll
            for (int e = 0; e < 4; ++e) acc[i][j][e] = 0.0f;

    // ---- prologue: B(0) via cp.async; A(0) via producer MMA; wait; sync ----
    {
        #pragma unroll
        for (int c = 0; c < 4; ++c)
            cpasync16(bRow + bcoff[c], w2p + c);
        asm volatile("cp.async.commit_group;" ::: "memory");

        #pragma unroll
        for (int t = 0; t < 4; ++t) {
            float2 w = *(const float2*)(W1 + (size_t)(8 * t + g) * 8 + 2 * tq);
            __half2 bh = __floats2half2_rn(w.x, w.y);
            uint32_t b0 = *(uint32_t*)&bh;
            float d[4];
            mma_f16_z(d, qf0, qf1, b0);
            __half2 h0 = __floats2half2_rn(fmaxf(d[0], 0.0f), fmaxf(d[1], 0.0f));
            __half2 h1 = __floats2half2_rn(fmaxf(d[2], 0.0f), fmaxf(d[3], 0.0f));
            sts32(pBase0 + ((((uint32_t)t) ^ sw0) << 4), *(uint32_t*)&h0);
            sts32(pBase1 + ((((uint32_t)t) ^ sw1) << 4), *(uint32_t*)&h1);
        }
        asm volatile("cp.async.wait_group 0;" ::: "memory");
    }
    __syncthreads();

    for (int it = 0; it < K_ITERS; ++it) {
        const int b = it & 1, nb = b ^ 1;
        const bool dp = (it + 1 < K_ITERS);
        const int kkn = (it + 1) * BK;

        // ---- kick off next B chunk (async, register-free) ----
        if (dp) {
            const uint32_t o = (uint32_t)nb * SBB;
            const uint4* src = w2p + (size_t)(kkn >> 3);
            #pragma unroll
            for (int c = 0; c < 4; ++c)
                cpasync16(bRow + o + bcoff[c], src + c);
            asm volatile("cp.async.commit_group;" ::: "memory");
        }

        // ---- issue W1 loads for next chunk early (L1-resident) ----
        float2 wv[4];
        if (dp) {
            #pragma unroll
            for (int t = 0; t < 4; ++t)
                wv[t] = *(const float2*)(W1 + (size_t)(kkn + 8 * t + g) * 8 + 2 * tq);
        }

        // ---- consume buffer b (R5-verified) ----
        const uint32_t aoff = (uint32_t)b * SAB;
        const uint32_t boff = (uint32_t)b * SBB;
        #pragma unroll
        for (int ks = 0; ks < 2; ++ks) {
            uint32_t a[4][4];
            #pragma unroll
            for (int im = 0; im < 4; ++im)
                ldsm4(a[im], aCbase + aoff + im * 1024 +
                             ((((uint32_t)(ks * 2 + aCk)) ^ aCs) << 4));
            uint32_t bb[4][4];
            #pragma unroll
            for (int jp = 0; jp < 4; ++jp)
                ldsm4(bb[jp], bCbase + boff + jp * 1024 +
                              ((((uint32_t)(ks * 2 + bCk)) ^ bCs) << 4));
            #pragma unroll
            for (int im = 0; im < 4; ++im)
                #pragma unroll
                for (int jn = 0; jn < 8; ++jn)
                    mma_f16(acc[im][jn], a[im],
                            bb[jn >> 1][(jn & 1) * 2], bb[jn >> 1][(jn & 1) * 2 + 1]);
        }

        // ---- produce A(it+1) via tensor core: H = relu(q . W1^T) ----
        if (dp) {
            const uint32_t o = (uint32_t)nb * SAB;
            #pragma unroll
            for (int t = 0; t < 4; ++t) {
                __half2 bh = __floats2half2_rn(wv[t].x, wv[t].y);
                uint32_t b0 = *(uint32_t*)&bh;
                float d[4];
                mma_f16_z(d, qf0, qf1, b0);
                __half2 h0 = __floats2half2_rn(fmaxf(d[0], 0.0f), fmaxf(d[1], 0.0f));
                __half2 h1 = __floats2half2_rn(fmaxf(d[2], 0.0f), fmaxf(d[3], 0.0f));
                sts32(pBase0 + o + ((((uint32_t)t) ^ sw0) << 4), *(uint32_t*)&h0);
                sts32(pBase1 + o + ((((uint32_t)t) ^ sw1) << 4), *(uint32_t*)&h1);
            }
            asm volatile("cp.async.wait_group 0;" ::: "memory");
        }
        __syncthreads();
    }

    // ---- epilogue: acc -> out (R5-verified mapping) ----
    #pragma unroll
    for (int im = 0; im < 4; ++im) {
        const int row0 = m0 + wm * 64 + im * 16 + g;
        #pragma unroll
        for (int jn = 0; jn < 8; ++jn) {
            const int col = n0 + wn * 64 + jn * 8 + tq * 2;
            *(float2*)(out + (size_t)row0 * E_DIM + col) =
                make_float2(acc[im][jn][0], acc[im][jn][1]);
            *(float2*)(out + (size_t)(row0 + 8) * E_DIM + col) =
                make_float2(acc[im][jn][2], acc[im][jn][3]);
        }
    }
}

extern "C" void kernel_launch(void* const* d_in, const int* in_sizes, int n_in,
                              void* d_out, int out_size) {
    const float* x     = (const float*)d_in[0];
    const float* theta = (const float*)d_in[1];
    const float* W1    = (const float*)d_in[2];
    const float* W2    = (const float*)d_in[3];
    float* out = (float*)d_out;

    cvt_w2_kernel<<<(E_DIM * F_DIM / 4) / 256, 256>>>(W2);

    cudaFuncSetAttribute(ffq_kernel, cudaFuncAttributeMaxDynamicSharedMemorySize, SMEM_BYTES);
    dim3 grid((M_TOTAL / BM) * (E_DIM / BN));   // 256 * 2 = 512 CTAs
    ffq_kernel<<<grid, THREADS, SMEM_BYTES>>>(x, theta, W1, out);
}

// round 16
// speedup vs baseline: 2.0464x; 1.3878x over previous
#include <cuda_runtime.h>
#include <cuda_fp16.h>
#include <math.h>
#include <stdint.h>

#define M_TOTAL 32768
#define E_DIM   512
#define F_DIM   2048

#define BM 128
#define BN 128
#define BK 32
#define THREADS 256
#define K_ITERS 64

// smem offsets (relative to 1024-aligned base)
#define SA0  0            // A (H fp16) [128 rows][64B] dbl: 2 x 8192
#define SAB  8192
#define SB0  16384        // B (W2 fp16) [128 rows][64B] dbl: 2 x 8192
#define SBB  8192
#define SMEM_BYTES (32768 + 1024)

// fp16 copy of W2 (E x F), row-major [n][k], uint4 = 8 halves
__device__ uint4 g_W2h[E_DIM * F_DIM / 8];

__global__ void cvt_w2_kernel(const float* __restrict__ W2) {
    int i = blockIdx.x * 256 + threadIdx.x;
    float4 v = ((const float4*)W2)[i];
    __half2* o = (__half2*)g_W2h;
    o[2 * i]     = __floats2half2_rn(v.x, v.y);
    o[2 * i + 1] = __floats2half2_rn(v.z, v.w);
}

static __device__ __forceinline__ uint32_t cvta_smem(const void* p) {
    uint32_t a;
    asm("{ .reg .u64 t; cvta.to.shared.u64 t, %1; cvt.u32.u64 %0, t; }" : "=r"(a) : "l"(p));
    return a;
}
static __device__ __forceinline__ void sts32(uint32_t addr, uint32_t v) {
    asm volatile("st.shared.b32 [%0], %1;" :: "r"(addr), "r"(v) : "memory");
}
static __device__ __forceinline__ void cpasync16(uint32_t dst, const void* src) {
    asm volatile("cp.async.ca.shared.global [%0], [%1], 16;"
                 :: "r"(dst), "l"(src) : "memory");
}
static __device__ __forceinline__ void ldsm4(uint32_t* r, uint32_t a) {
    asm volatile("ldmatrix.sync.aligned.m8n8.x4.shared.b16 {%0,%1,%2,%3}, [%4];"
                 : "=r"(r[0]), "=r"(r[1]), "=r"(r[2]), "=r"(r[3]) : "r"(a));
}
static __device__ __forceinline__ void mma_f16(float* c, const uint32_t* a,
                                               uint32_t b0, uint32_t b1) {
    asm volatile(
        "mma.sync.aligned.m16n8k16.row.col.f32.f16.f16.f32 "
        "{%0,%1,%2,%3},{%4,%5,%6,%7},{%8,%9},{%0,%1,%2,%3};"
        : "+f"(c[0]), "+f"(c[1]), "+f"(c[2]), "+f"(c[3])
        : "r"(a[0]), "r"(a[1]), "r"(a[2]), "r"(a[3]), "r"(b0), "r"(b1));
}
// d = A(k16, upper 8 zero) * B(n8k16, upper k zero); c = 0
static __device__ __forceinline__ void mma_f16_z(float* d, uint32_t a0, uint32_t a1,
                                                 uint32_t b0) {
    asm volatile(
        "mma.sync.aligned.m16n8k16.row.col.f32.f16.f16.f32 "
        "{%0,%1,%2,%3},{%4,%5,%6,%6},{%7,%6},{%8,%8,%8,%8};"
        : "=f"(d[0]), "=f"(d[1]), "=f"(d[2]), "=f"(d[3])
        : "r"(a0), "r"(a1), "r"(0u), "r"(b0), "f"(0.0f));
}

__global__ void __launch_bounds__(THREADS, 2)
ffq_kernel(const float* __restrict__ x,
           const float* __restrict__ theta,
           const float* __restrict__ W1,
           float* __restrict__ out)
{
    extern __shared__ char dsm[];
    const uint32_t raw = cvta_smem(dsm);
    const uint32_t sbase = (raw + 1023) & ~1023u;

    const int tid  = threadIdx.x;
    const int warp = tid >> 5, lane = tid & 31;
    const int g = lane >> 2, tq = lane & 3;
    const int wm = warp >> 2, wn = warp & 3;     // consumer: 2 x 4 grid, warp tile 64x32
    const int mt = blockIdx.x >> 2, nt = blockIdx.x & 3;
    const int m0 = mt * BM, n0 = nt * BN;

    // ---- q A-fragment (computed once): rows pr, pr+8; k = 2tq, 2tq+1 ----
    const int pr = warp * 16 + g;                // 0..127 across 8 warps
    uint32_t qf0, qf1;
    {
        const float t0 = __ldg(theta + 2 * tq);
        const float t1 = __ldg(theta + 2 * tq + 1);
        float2 v0 = *(const float2*)(x + (size_t)(m0 + pr) * E_DIM + 2 * tq);
        float2 v1 = *(const float2*)(x + (size_t)(m0 + pr + 8) * E_DIM + 2 * tq);
        __half2 h0 = __floats2half2_rn(cosf(2.0f * v0.x + t0), cosf(2.0f * v0.y + t1));
        __half2 h1 = __floats2half2_rn(cosf(2.0f * v1.x + t0), cosf(2.0f * v1.y + t1));
        qf0 = *(uint32_t*)&h0;
        qf1 = *(uint32_t*)&h1;
    }

    // ---- A producer STS bases (R10-verified layout: [128 rows][64B], swz (row>>1)&3) ----
    const uint32_t sw0 = (uint32_t)((pr >> 1) & 3);
    const uint32_t sw1 = (uint32_t)(((pr + 8) >> 1) & 3);
    const uint32_t pBase0 = sbase + SA0 + pr * 64 + tq * 4;
    const uint32_t pBase1 = sbase + SA0 + (pr + 8) * 64 + tq * 4;

    // ---- B producer (R6-verified): thread covers rows bnr, bnr+64; 16B col bc ----
    const int bnr = tid >> 2, bc = tid & 3;
    const uint32_t bDst0 = sbase + SB0 + bnr * 64 +
                           (((uint32_t)(bc ^ ((bnr >> 1) & 3))) << 4);
    const uint32_t bDst1 = sbase + SB0 + (bnr + 64) * 64 +
                           (((uint32_t)(bc ^ (((bnr + 64) >> 1) & 3))) << 4);
    const uint4* w2p0 = g_W2h + (size_t)(n0 + bnr) * 256 + bc;
    const uint4* w2p1 = g_W2h + (size_t)(n0 + bnr + 64) * 256 + bc;

    // ---- consumer constants (R6-verified 64x32 mapping) ----
    const int t8 = lane >> 3, r8 = lane & 7;
    const int aCrow = wm * 64 + (t8 & 1) * 8 + r8;
    const uint32_t aCs = (aCrow >> 1) & 3;
    const uint32_t aCbase = sbase + SA0 + aCrow * 64;
    const int aCk = t8 >> 1;
    const int bCrow = wn * 32 + (t8 >> 1) * 8 + r8;
    const uint32_t bCs = (bCrow >> 1) & 3;
    const uint32_t bCbase = sbase + SB0 + bCrow * 64;
    const int bCk = t8 & 1;

    float acc[4][4][4];
    #pragma unroll
    for (int i = 0; i < 4; ++i)
        #pragma unroll
        for (int j = 0; j < 4; ++j)
            #pragma unroll
            for (int e = 0; e < 4; ++e) acc[i][j][e] = 0.0f;

    // ---- prologue: B(0) via cp.async; A(0) via producer MMA; wait; sync ----
    {
        cpasync16(bDst0, w2p0);
        cpasync16(bDst1, w2p1);
        asm volatile("cp.async.commit_group;" ::: "memory");

        #pragma unroll
        for (int t = 0; t < 4; ++t) {
            float2 w = *(const float2*)(W1 + (size_t)(8 * t + g) * 8 + 2 * tq);
            __half2 bh = __floats2half2_rn(w.x, w.y);
            float d[4];
            mma_f16_z(d, qf0, qf1, *(uint32_t*)&bh);
            __half2 h0 = __floats2half2_rn(fmaxf(d[0], 0.0f), fmaxf(d[1], 0.0f));
            __half2 h1 = __floats2half2_rn(fmaxf(d[2], 0.0f), fmaxf(d[3], 0.0f));
            sts32(pBase0 + ((((uint32_t)t) ^ sw0) << 4), *(uint32_t*)&h0);
            sts32(pBase1 + ((((uint32_t)t) ^ sw1) << 4), *(uint32_t*)&h1);
        }
        asm volatile("cp.async.wait_group 0;" ::: "memory");
    }
    __syncthreads();

    for (int it = 0; it < K_ITERS; ++it) {
        const int b = it & 1, nb = b ^ 1;
        const bool dp = (it + 1 < K_ITERS);
        const int kkn = (it + 1) * BK;

        // ---- top: kick off B(it+1) and produce A(it+1) (no smem reads) ----
        if (dp) {
            const uint32_t o = (uint32_t)nb * SBB;
            cpasync16(bDst0 + o, w2p0 + (kkn >> 3));
            cpasync16(bDst1 + o, w2p1 + (kkn >> 3));
            asm volatile("cp.async.commit_group;" ::: "memory");

            const uint32_t oa = (uint32_t)nb * SAB;
            #pragma unroll
            for (int t = 0; t < 4; ++t) {
                float2 w = *(const float2*)(W1 + (size_t)(kkn + 8 * t + g) * 8 + 2 * tq);
                __half2 bh = __floats2half2_rn(w.x, w.y);
                float d[4];
                mma_f16_z(d, qf0, qf1, *(uint32_t*)&bh);
                __half2 h0 = __floats2half2_rn(fmaxf(d[0], 0.0f), fmaxf(d[1], 0.0f));
                __half2 h1 = __floats2half2_rn(fmaxf(d[2], 0.0f), fmaxf(d[3], 0.0f));
                sts32(pBase0 + oa + ((((uint32_t)t) ^ sw0) << 4), *(uint32_t*)&h0);
                sts32(pBase1 + oa + ((((uint32_t)t) ^ sw1) << 4), *(uint32_t*)&h1);
            }
        }

        // ---- consume buffer b (R6-verified) ----
        const uint32_t aoff = (uint32_t)b * SAB;
        const uint32_t boff = (uint32_t)b * SBB;
        #pragma unroll
        for (int ks = 0; ks < 2; ++ks) {
            uint32_t a[4][4];
            #pragma unroll
            for (int im = 0; im < 4; ++im)
                ldsm4(a[im], aCbase + aoff + im * 1024 +
                             ((((uint32_t)(ks * 2 + aCk)) ^ aCs) << 4));
            uint32_t bb[2][4];
            #pragma unroll
            for (int jp = 0; jp < 2; ++jp)
                ldsm4(bb[jp], bCbase + boff + jp * 1024 +
                              ((((uint32_t)(ks * 2 + bCk)) ^ bCs) << 4));
            #pragma unroll
            for (int im = 0; im < 4; ++im)
                #pragma unroll
                for (int jn = 0; jn < 4; ++jn)
                    mma_f16(acc[im][jn], a[im],
                            bb[jn >> 1][(jn & 1) * 2], bb[jn >> 1][(jn & 1) * 2 + 1]);
        }

        if (dp) asm volatile("cp.async.wait_group 0;" ::: "memory");
        __syncthreads();
    }

    // ---- epilogue (R6-verified) ----
    #pragma unroll
    for (int im = 0; im < 4; ++im) {
        const int row0 = m0 + wm * 64 + im * 16 + g;
        #pragma unroll
        for (int jn = 0; jn < 4; ++jn) {
            const int col = n0 + wn * 32 + jn * 8 + tq * 2;
            *(float2*)(out + (size_t)row0 * E_DIM + col) =
                make_float2(acc[im][jn][0], acc[im][jn][1]);
            *(float2*)(out + (size_t)(row0 + 8) * E_DIM + col) =
                make_float2(acc[im][jn][2], acc[im][jn][3]);
        }
    }
}

extern "C" void kernel_launch(void* const* d_in, const int* in_sizes, int n_in,
                              void* d_out, int out_size) {
    const float* x     = (const float*)d_in[0];
    const float* theta = (const float*)d_in[1];
    const float* W1    = (const float*)d_in[2];
    const float* W2    = (const float*)d_in[3];
    float* out = (float*)d_out;

    cvt_w2_kernel<<<(E_DIM * F_DIM / 4) / 256, 256>>>(W2);

    cudaFuncSetAttribute(ffq_kernel, cudaFuncAttributeMaxDynamicSharedMemorySize, SMEM_BYTES);
    dim3 grid((M_TOTAL / BM) * (E_DIM / BN));   // 256 * 4 = 1024 CTAs
    ffq_kernel<<<grid, THREADS, SMEM_BYTES>>>(x, theta, W1, out);
}